// round 15
// baseline (speedup 1.0000x reference)
#include <cuda_runtime.h>
#include <cuda_bf16.h>
#include <math.h>
#include <stdint.h>

#define NUM_CLASSES 19
#define KPC 100
#define NA 1900
#define NA_PAD 1920
#define NMEM 20000
#define NCOLS 21900
#define NC_PAD 21952
#define DIMS 256
#define HW 16384
#define LBLK 1024
#define NLBLK 128
#define ROW_TILES 15
#define COL_CHUNKS 20
#define NSUB 343
#define NBLOCKS (COL_CHUNKS * ROW_TILES)
#define TEMP_INV 10.0f
#define L2E10 14.426950408889634f
#define LOSS_SCALE 1.4285714285714286f

// -------------------- device scratch --------------------
__device__ int g_lab64;
__device__ int g_idx[NA];
__device__ int g_cnt[NUM_CLASSES];
__device__ unsigned g_done;
__device__ __align__(16) __nv_bfloat16 g_A[NA_PAD * DIMS];
__device__ __align__(16) __nv_bfloat16 g_C[NC_PAD * DIMS];
__device__ int g_clab[NC_PAD];
__device__ float g_Sp[NA_PAD * COL_CHUNKS];
__device__ float g_Pp[NA_PAD * COL_CHUNKS];

__device__ __forceinline__ int load_label(const void* p, int i) {
    if (g_lab64) return (int)((const long long*)p)[i];
    return ((const int*)p)[i];
}

// MUFU-based exp-and-accumulate: S += 2^(acc*10*log2e), P += acc if labels match.
__device__ __forceinline__ void ep_core(float acc_v, int labv, int rl, float& S, float& P) {
    float e;
    asm("ex2.approx.f32 %0, %1;" : "=f"(e) : "f"(acc_v * L2E10));
    S += e;
    if (labv == rl) P += acc_v;
}

__device__ __forceinline__ void mma_bf16(float* d, const unsigned* a, const unsigned* b) {
    asm volatile(
        "mma.sync.aligned.m16n8k16.row.col.f32.bf16.bf16.f32 "
        "{%0,%1,%2,%3}, {%4,%5,%6,%7}, {%8,%9}, {%0,%1,%2,%3};\n"
        : "+f"(d[0]), "+f"(d[1]), "+f"(d[2]), "+f"(d[3])
        : "r"(a[0]), "r"(a[1]), "r"(a[2]), "r"(a[3]), "r"(b[0]), "r"(b[1]));
}

__device__ __forceinline__ void ldsm_x4(unsigned& r0, unsigned& r1, unsigned& r2,
                                        unsigned& r3, unsigned addr) {
    asm volatile("ldmatrix.sync.aligned.m8n8.x4.shared.b16 {%0,%1,%2,%3}, [%4];"
                 : "=r"(r0), "=r"(r1), "=r"(r2), "=r"(r3) : "r"(addr));
}

// -------------------- fused sampling + ballot histogram ------------
__global__ void k_sample(const int* lab32, const void* labels, const void* mlab) {
    __shared__ int slab[LBLK];
    __shared__ int sbad;
    __shared__ int squit;
    __shared__ int scnt[NUM_CLASSES];
    int tid  = threadIdx.x;
    int lane = tid & 31;
    int w    = tid >> 5;

    if (tid == 0) sbad = 0;
    if (tid < NUM_CLASSES) scnt[tid] = 0;
    __syncthreads();
    if (lab32[2 * tid + 1] != 0) sbad = 1;
    __syncthreads();
    const int is64 = (sbad == 0) ? 1 : 0;
    if (tid == 0) g_lab64 = is64;

    // contention-free histogram: warp-ballot counting, lane c owns class c
    {
        int myCount = 0;   // count of class==lane (lanes 0..18 meaningful)
        #pragma unroll 4
        for (int i = tid; i < 20480; i += 1024) {       // 20 iterations for all threads
            int lv = -1;
            if (i < NMEM)
                lv = is64 ? (int)((const long long*)mlab)[i] : ((const int*)mlab)[i];
            #pragma unroll
            for (int c = 0; c < NUM_CLASSES; c++) {
                unsigned m = __ballot_sync(0xffffffffu, lv == c);
                if (lane == c) myCount += __popc(m);
            }
        }
        if (lane < NUM_CLASSES) atomicAdd(&scnt[lane], myCount);
    }

    int r = 0;
    unsigned below = (1u << lane) - 1u;

    for (int c = 0; c < NLBLK; c++) {
        int base = c * LBLK;
        int v;
        if (is64) v = (int)((const long long*)labels)[base + tid];
        else      v = ((const int*)labels)[base + tid];
        if (tid == 0) squit = 1;
        slab[tid] = v;
        __syncthreads();

        if (w < NUM_CLASSES && r < KPC) {
            #pragma unroll 4
            for (int s = 0; s < 32; s++) {
                int lv = slab[s * 32 + lane];
                unsigned m = __ballot_sync(0xffffffffu, lv == w);
                if (lv == w) {
                    int rank = r + __popc(m & below);
                    if (rank < KPC) g_idx[w * KPC + rank] = base + s * 32 + lane;
                }
                r += __popc(m);
                if (r >= KPC) break;
            }
        }
        if (w < NUM_CLASSES && lane == 0 && r < KPC) squit = 0;
        __syncthreads();
        if (squit) break;
    }
    __syncthreads();
    if (tid < NUM_CLASSES) g_cnt[tid] = scnt[tid];
}

// -------------------- fused gather/normalize: anchors + memory ------------
#define ANCHOR_BLOCKS (NA_PAD / 8)
#define MEM_BLOCKS ((NC_PAD - NA + 7) / 8)

__global__ void k_prep(const float* __restrict__ pf, const float* __restrict__ mf,
                       const void* mlab) {
    int wid  = threadIdx.x >> 5;
    int lane = threadIdx.x & 31;

    if (blockIdx.x < ANCHOR_BLOCKS) {
        int n = blockIdx.x * 8 + wid;
        float v[8];
        if (n < NA) {
            int idx = g_idx[n];
            int b   = idx >> 14;
            int rem = idx & (HW - 1);
            const float* src = pf + (size_t)b * (DIMS * HW) + rem;
            #pragma unroll
            for (int j = 0; j < 8; j++)
                v[j] = src[(size_t)(lane + 32 * j) * HW];
        } else {
            #pragma unroll
            for (int j = 0; j < 8; j++) v[j] = 0.f;
        }
        float ss = 0.f;
        #pragma unroll
        for (int j = 0; j < 8; j++) ss += v[j] * v[j];
        #pragma unroll
        for (int o = 16; o; o >>= 1) ss += __shfl_xor_sync(0xffffffffu, ss, o);
        float sc = (n < NA) ? (1.f / fmaxf(sqrtf(ss), 1e-12f)) : 0.f;
        #pragma unroll
        for (int j = 0; j < 8; j++) {
            __nv_bfloat16 o16 = __float2bfloat16(v[j] * sc);
            int d = lane + 32 * j;
            g_A[n * DIMS + d] = o16;
            g_C[n * DIMS + d] = o16;
        }
        if (lane == 0 && n < NA) g_clab[n] = n / KPC;
    } else {
        int m = (blockIdx.x - ANCHOR_BLOCKS) * 8 + wid;
        if (m >= NC_PAD - NA) return;
        float v[8];
        if (m < NMEM) {
            const float* src = mf + (size_t)m * DIMS;
            #pragma unroll
            for (int j = 0; j < 8; j++) v[j] = src[lane + 32 * j];
        } else {
            #pragma unroll
            for (int j = 0; j < 8; j++) v[j] = 0.f;
        }
        float ss = 0.f;
        #pragma unroll
        for (int j = 0; j < 8; j++) ss += v[j] * v[j];
        #pragma unroll
        for (int o = 16; o; o >>= 1) ss += __shfl_xor_sync(0xffffffffu, ss, o);
        float sc = (m < NMEM) ? (1.f / fmaxf(sqrtf(ss), 1e-12f)) : 0.f;
        #pragma unroll
        for (int j = 0; j < 8; j++)
            g_C[(size_t)(NA + m) * DIMS + lane + 32 * j] = __float2bfloat16(v[j] * sc);
        if (lane == 0)
            g_clab[NA + m] = (m < NMEM) ? load_label(mlab, m) : -1;
    }
}

// -------------------- fused GEMM + softmax reductions + last-block final ----
extern __shared__ char smem_raw[];

#define AS_BYTES (128 * 264 * 2)
#define CS_BYTES (64 * 264 * 2)
#define SMEM_BYTES (AS_BYTES + CS_BYTES + 64 * 4 + 2 * 256 * 4)

__global__ void __launch_bounds__(256) k_main(float* __restrict__ out) {
    __nv_bfloat16* As = (__nv_bfloat16*)smem_raw;                        // [128][264]
    __nv_bfloat16* Cs = (__nv_bfloat16*)(smem_raw + AS_BYTES);           // [64][264]
    int*   clab_sm = (int*)(smem_raw + AS_BYTES + CS_BYTES);             // [64]
    float* redS    = (float*)(smem_raw + AS_BYTES + CS_BYTES + 64 * 4);  // [128][2]
    float* redP    = redS + 256;

    const int tid     = threadIdx.x;
    const int chunk   = blockIdx.x;
    const int rowbase = blockIdx.y * 128;
    const int lane = tid & 31;
    const int w    = tid >> 5;
    const int wr   = w >> 1;
    const int wc   = w & 1;
    const int g    = lane >> 2;
    const int t2   = (lane & 3) * 2;

    const int ld_row = tid >> 5;
    const int ld_kv  = tid & 31;

    // A tile [128][256]
    #pragma unroll
    for (int it = 0; it < 16; it++) {
        int lin = tid + it * 256;
        int row = lin >> 5;
        int kv  = lin & 31;
        *(uint4*)(As + row * 264 + kv * 8) =
            *(const uint4*)(g_A + (size_t)(rowbase + row) * DIMS + kv * 8);
    }

    unsigned as_u32 = (unsigned)__cvta_generic_to_shared(As);
    unsigned cs_u32 = (unsigned)__cvta_generic_to_shared(Cs);
    unsigned aAddr[2], bAddr[2];
    {
        int arow = (lane & 7) + ((lane >> 3) & 1) * 8;
        int acol = (lane >> 4) * 8;
        #pragma unroll
        for (int mb = 0; mb < 2; mb++)
            aAddr[mb] = as_u32 + ((wr * 32 + mb * 16 + arow) * 264 + acol) * 2;
        int brow = ((lane >> 4) & 1) * 8 + (lane & 7);
        int bcol = ((lane >> 3) & 1) * 8;
        #pragma unroll
        for (int pr = 0; pr < 2; pr++)
            bAddr[pr] = cs_u32 + ((wc * 32 + pr * 16 + brow) * 264 + bcol) * 2;
    }

    float Sacc[2][2] = {{0.f, 0.f}, {0.f, 0.f}};
    float Pacc[2][2] = {{0.f, 0.f}, {0.f, 0.f}};
    int rlab[2][2], grow[2][2];
    #pragma unroll
    for (int mb = 0; mb < 2; mb++)
        #pragma unroll
        for (int p = 0; p < 2; p++) {
            int r = rowbase + wr * 32 + mb * 16 + g + 8 * p;
            grow[mb][p] = r;
            rlab[mb][p] = (r < NA) ? (r / KPC) : -2;
        }

    // prefetch first subtile into registers
    uint4 pre[8];
    int   prelab = 0;
    {
        const int colbase = chunk * 64;
        #pragma unroll
        for (int it = 0; it < 8; it++)
            pre[it] = *(const uint4*)(g_C + (size_t)(colbase + ld_row + it * 8) * DIMS + ld_kv * 8);
        if (tid < 64) prelab = g_clab[colbase + tid];
    }

    for (int s = chunk; s < NSUB; s += COL_CHUNKS) {
        const int colbase = s * 64;
        const bool edge = (colbase + 64 > NCOLS) ||
                          ((colbase < rowbase + 128) && (colbase + 64 > rowbase));
        __syncthreads();
        #pragma unroll
        for (int it = 0; it < 8; it++)
            *(uint4*)(Cs + (ld_row + it * 8) * 264 + ld_kv * 8) = pre[it];
        if (tid < 64) clab_sm[tid] = prelab;
        __syncthreads();

        const int ns = s + COL_CHUNKS;
        if (ns < NSUB) {
            const int ncb = ns * 64;
            #pragma unroll
            for (int it = 0; it < 8; it++)
                pre[it] = *(const uint4*)(g_C + (size_t)(ncb + ld_row + it * 8) * DIMS + ld_kv * 8);
            if (tid < 64) prelab = g_clab[ncb + tid];
        }

        float acc[2][4][4];
        #pragma unroll
        for (int mb = 0; mb < 2; mb++)
            #pragma unroll
            for (int nb = 0; nb < 4; nb++)
                #pragma unroll
                for (int q = 0; q < 4; q++) acc[mb][nb][q] = 0.f;

        #pragma unroll
        for (int k = 0; k < DIMS; k += 16) {
            unsigned a[2][4], b[4][2];
            #pragma unroll
            for (int mb = 0; mb < 2; mb++)
                ldsm_x4(a[mb][0], a[mb][1], a[mb][2], a[mb][3], aAddr[mb] + k * 2);
            #pragma unroll
            for (int pr = 0; pr < 2; pr++)
                ldsm_x4(b[2 * pr][0], b[2 * pr][1], b[2 * pr + 1][0], b[2 * pr + 1][1],
                        bAddr[pr] + k * 2);
            #pragma unroll
            for (int mb = 0; mb < 2; mb++)
                #pragma unroll
                for (int nb = 0; nb < 4; nb++)
                    mma_bf16(acc[mb][nb], a[mb], b[nb]);
        }

        int labreg[8];
        #pragma unroll
        for (int nb = 0; nb < 4; nb++)
            #pragma unroll
            for (int e = 0; e < 2; e++)
                labreg[nb * 2 + e] = clab_sm[wc * 32 + nb * 8 + t2 + e];

        if (!edge) {
            #pragma unroll
            for (int mb = 0; mb < 2; mb++)
                #pragma unroll
                for (int nb = 0; nb < 4; nb++)
                    #pragma unroll
                    for (int p = 0; p < 2; p++)
                        #pragma unroll
                        for (int e = 0; e < 2; e++)
                            ep_core(acc[mb][nb][2 * p + e], labreg[nb * 2 + e],
                                    rlab[mb][p], Sacc[mb][p], Pacc[mb][p]);
        } else {
            #pragma unroll
            for (int mb = 0; mb < 2; mb++)
                #pragma unroll
                for (int nb = 0; nb < 4; nb++) {
                    int colb = wc * 32 + nb * 8 + t2;
                    #pragma unroll
                    for (int p = 0; p < 2; p++)
                        #pragma unroll
                        for (int e = 0; e < 2; e++) {
                            int gcol = colbase + colb + e;
                            if (gcol < NCOLS && gcol != grow[mb][p])
                                ep_core(acc[mb][nb][2 * p + e], labreg[nb * 2 + e],
                                        rlab[mb][p], Sacc[mb][p], Pacc[mb][p]);
                        }
                }
        }
    }

    #pragma unroll
    for (int mb = 0; mb < 2; mb++)
        #pragma unroll
        for (int p = 0; p < 2; p++) {
            float sv = Sacc[mb][p], pv = Pacc[mb][p];
            sv += __shfl_xor_sync(0xffffffffu, sv, 1);
            sv += __shfl_xor_sync(0xffffffffu, sv, 2);
            pv += __shfl_xor_sync(0xffffffffu, pv, 1);
            pv += __shfl_xor_sync(0xffffffffu, pv, 2);
            if ((lane & 3) == 0) {
                int row = wr * 32 + mb * 16 + g + 8 * p;
                redS[row * 2 + wc] = sv;
                redP[row * 2 + wc] = pv;
            }
        }
    __syncthreads();
    if (tid < 128) {
        int r = rowbase + tid;
        g_Sp[r * COL_CHUNKS + chunk] = redS[tid * 2] + redS[tid * 2 + 1];
        g_Pp[r * COL_CHUNKS + chunk] = redP[tid * 2] + redP[tid * 2 + 1];
    }

    // ---- last-block final reduction ----
    __shared__ int sdone;
    __syncthreads();
    __threadfence();
    if (tid == 0) {
        unsigned v = atomicAdd(&g_done, 1u);
        sdone = (v == NBLOCKS - 1);
    }
    __syncthreads();
    if (!sdone) return;

    float local = 0.f;
    for (int n = tid; n < NA; n += 256) {
        float S = 0.f, P = 0.f;
        #pragma unroll
        for (int ch = 0; ch < COL_CHUNKS; ch++) {
            S += g_Sp[n * COL_CHUNKS + ch];
            P += g_Pp[n * COL_CHUNKS + ch];
        }
        float cnt = (float)(KPC - 1 + g_cnt[n / KPC]);
        local += (TEMP_INV * P - cnt * logf(S + 1e-12f)) / cnt;
    }
    redS[tid] = local;
    __syncthreads();
    for (int off = 128; off; off >>= 1) {
        if (tid < off) redS[tid] += redS[tid + off];
        __syncthreads();
    }
    if (tid == 0) {
        out[0] = -LOSS_SCALE * redS[0] / (float)NA;
        g_done = 0;                     // reset for next graph replay
    }
}

// -------------------- launch --------------------
extern "C" void kernel_launch(void* const* d_in, const int* in_sizes, int n_in,
                              void* d_out, int out_size) {
    (void)in_sizes; (void)n_in; (void)out_size;
    const float* pf   = (const float*)d_in[0];
    const void*  lab  = d_in[1];
    const float* mf   = (const float*)d_in[2];
    const void*  mlab = d_in[3];
    float* out = (float*)d_out;

    cudaFuncSetAttribute(k_main, cudaFuncAttributeMaxDynamicSharedMemorySize, SMEM_BYTES);

    k_sample<<<1, 1024>>>((const int*)lab, lab, mlab);
    k_prep<<<ANCHOR_BLOCKS + MEM_BLOCKS, 256>>>(pf, mf, mlab);
    k_main<<<dim3(COL_CHUNKS, ROW_TILES), 256, SMEM_BYTES>>>(out);
}

// round 16
// speedup vs baseline: 1.0192x; 1.0192x over previous
#include <cuda_runtime.h>
#include <cuda_bf16.h>
#include <math.h>
#include <stdint.h>

#define NUM_CLASSES 19
#define KPC 100
#define NA 1900
#define NA_PAD 1920
#define NMEM 20000
#define NCOLS 21900
#define NC_PAD 21952
#define DIMS 256
#define HW 16384
#define LBLK 1024
#define NLBLK 128
#define ROW_TILES 15
#define COL_CHUNKS 20
#define NSUB 343
#define NBLOCKS (COL_CHUNKS * ROW_TILES)
#define TEMP_INV 10.0f
#define L2E10 14.426950408889634f
#define LOSS_SCALE 1.4285714285714286f

// -------------------- device scratch --------------------
__device__ int g_lab64;
__device__ int g_idx[NA];
__device__ int g_cnt[NUM_CLASSES];
__device__ unsigned g_done;
__device__ __align__(16) __nv_bfloat16 g_A[NA_PAD * DIMS];
__device__ __align__(16) __nv_bfloat16 g_C[NC_PAD * DIMS];
__device__ int g_clab[NC_PAD];
__device__ float g_Sp[NA_PAD * COL_CHUNKS];
__device__ float g_Pp[NA_PAD * COL_CHUNKS];

__device__ __forceinline__ int load_label(const void* p, int i) {
    if (g_lab64) return (int)((const long long*)p)[i];
    return ((const int*)p)[i];
}

// MUFU-based exp-and-accumulate: S += 2^(acc*10*log2e), P += acc if labels match.
__device__ __forceinline__ void ep_core(float acc_v, int labv, int rl, float& S, float& P) {
    float e;
    asm("ex2.approx.f32 %0, %1;" : "=f"(e) : "f"(acc_v * L2E10));
    S += e;
    if (labv == rl) P += acc_v;
}

__device__ __forceinline__ void mma_bf16(float* d, const unsigned* a, const unsigned* b) {
    asm volatile(
        "mma.sync.aligned.m16n8k16.row.col.f32.bf16.bf16.f32 "
        "{%0,%1,%2,%3}, {%4,%5,%6,%7}, {%8,%9}, {%0,%1,%2,%3};\n"
        : "+f"(d[0]), "+f"(d[1]), "+f"(d[2]), "+f"(d[3])
        : "r"(a[0]), "r"(a[1]), "r"(a[2]), "r"(a[3]), "r"(b[0]), "r"(b[1]));
}

__device__ __forceinline__ void ldsm_x4(unsigned& r0, unsigned& r1, unsigned& r2,
                                        unsigned& r3, unsigned addr) {
    asm volatile("ldmatrix.sync.aligned.m8n8.x4.shared.b16 {%0,%1,%2,%3}, [%4];"
                 : "=r"(r0), "=r"(r1), "=r"(r2), "=r"(r3) : "r"(addr));
}

// -------------------- fused sampling (detect + scan only) ------------
__global__ void k_sample(const int* lab32, const void* labels) {
    __shared__ int slab[LBLK];
    __shared__ int sbad;
    __shared__ int squit;
    int tid  = threadIdx.x;
    int lane = tid & 31;
    int w    = tid >> 5;

    if (tid == 0) { sbad = 0; g_done = 0; }
    if (tid < NUM_CLASSES) g_cnt[tid] = 0;     // zeroed before k_prep's atomics
    __syncthreads();
    if (lab32[2 * tid + 1] != 0) sbad = 1;
    __syncthreads();
    const int is64 = (sbad == 0) ? 1 : 0;
    if (tid == 0) g_lab64 = is64;

    int r = 0;
    unsigned below = (1u << lane) - 1u;

    for (int c = 0; c < NLBLK; c++) {
        int base = c * LBLK;
        int v;
        if (is64) v = (int)((const long long*)labels)[base + tid];
        else      v = ((const int*)labels)[base + tid];
        if (tid == 0) squit = 1;
        slab[tid] = v;
        __syncthreads();

        if (w < NUM_CLASSES && r < KPC) {
            #pragma unroll 4
            for (int s = 0; s < 32; s++) {
                int lv = slab[s * 32 + lane];
                unsigned m = __ballot_sync(0xffffffffu, lv == w);
                if (lv == w) {
                    int rank = r + __popc(m & below);
                    if (rank < KPC) g_idx[w * KPC + rank] = base + s * 32 + lane;
                }
                r += __popc(m);
                if (r >= KPC) break;
            }
        }
        if (w < NUM_CLASSES && lane == 0 && r < KPC) squit = 0;
        __syncthreads();
        if (squit) break;
    }
}

// -------------------- fused gather/normalize: anchors + memory + histogram ----
#define ANCHOR_BLOCKS (NA_PAD / 8)
#define MEM_BLOCKS ((NC_PAD - NA + 7) / 8)

__global__ void k_prep(const float* __restrict__ pf, const float* __restrict__ mf,
                       const void* mlab) {
    int wid  = threadIdx.x >> 5;
    int lane = threadIdx.x & 31;

    if (blockIdx.x < ANCHOR_BLOCKS) {
        int n = blockIdx.x * 8 + wid;
        float v[8];
        if (n < NA) {
            int idx = g_idx[n];
            int b   = idx >> 14;
            int rem = idx & (HW - 1);
            const float* src = pf + (size_t)b * (DIMS * HW) + rem;
            #pragma unroll
            for (int j = 0; j < 8; j++)
                v[j] = src[(size_t)(lane + 32 * j) * HW];
        } else {
            #pragma unroll
            for (int j = 0; j < 8; j++) v[j] = 0.f;
        }
        float ss = 0.f;
        #pragma unroll
        for (int j = 0; j < 8; j++) ss += v[j] * v[j];
        #pragma unroll
        for (int o = 16; o; o >>= 1) ss += __shfl_xor_sync(0xffffffffu, ss, o);
        float sc = (n < NA) ? (1.f / fmaxf(sqrtf(ss), 1e-12f)) : 0.f;
        #pragma unroll
        for (int j = 0; j < 8; j++) {
            __nv_bfloat16 o16 = __float2bfloat16(v[j] * sc);
            int d = lane + 32 * j;
            g_A[n * DIMS + d] = o16;
            g_C[n * DIMS + d] = o16;
        }
        if (lane == 0 && n < NA) g_clab[n] = n / KPC;
    } else {
        int m = (blockIdx.x - ANCHOR_BLOCKS) * 8 + wid;
        if (m >= NC_PAD - NA) return;
        float v[8];
        if (m < NMEM) {
            const float* src = mf + (size_t)m * DIMS;
            #pragma unroll
            for (int j = 0; j < 8; j++) v[j] = src[lane + 32 * j];
        } else {
            #pragma unroll
            for (int j = 0; j < 8; j++) v[j] = 0.f;
        }
        float ss = 0.f;
        #pragma unroll
        for (int j = 0; j < 8; j++) ss += v[j] * v[j];
        #pragma unroll
        for (int o = 16; o; o >>= 1) ss += __shfl_xor_sync(0xffffffffu, ss, o);
        float sc = (m < NMEM) ? (1.f / fmaxf(sqrtf(ss), 1e-12f)) : 0.f;
        #pragma unroll
        for (int j = 0; j < 8; j++)
            g_C[(size_t)(NA + m) * DIMS + lane + 32 * j] = __float2bfloat16(v[j] * sc);
        if (lane == 0) {
            int lab = (m < NMEM) ? load_label(mlab, m) : -1;
            g_clab[NA + m] = lab;
            if (lab >= 0) atomicAdd(&g_cnt[lab], 1);     // spread global histogram
        }
    }
}

// -------------------- fused GEMM + softmax reductions + last-block final ----
extern __shared__ char smem_raw[];

#define AS_BYTES (128 * 264 * 2)
#define CS_BYTES (64 * 264 * 2)
#define SMEM_BYTES (AS_BYTES + CS_BYTES + 64 * 4 + 2 * 256 * 4)

__global__ void __launch_bounds__(256) k_main(float* __restrict__ out) {
    __nv_bfloat16* As = (__nv_bfloat16*)smem_raw;                        // [128][264]
    __nv_bfloat16* Cs = (__nv_bfloat16*)(smem_raw + AS_BYTES);           // [64][264]
    int*   clab_sm = (int*)(smem_raw + AS_BYTES + CS_BYTES);             // [64]
    float* redS    = (float*)(smem_raw + AS_BYTES + CS_BYTES + 64 * 4);  // [128][2]
    float* redP    = redS + 256;

    const int tid     = threadIdx.x;
    const int chunk   = blockIdx.x;
    const int rowbase = blockIdx.y * 128;
    const int lane = tid & 31;
    const int w    = tid >> 5;
    const int wr   = w >> 1;
    const int wc   = w & 1;
    const int g    = lane >> 2;
    const int t2   = (lane & 3) * 2;

    const int ld_row = tid >> 5;
    const int ld_kv  = tid & 31;

    // A tile [128][256]
    #pragma unroll
    for (int it = 0; it < 16; it++) {
        int lin = tid + it * 256;
        int row = lin >> 5;
        int kv  = lin & 31;
        *(uint4*)(As + row * 264 + kv * 8) =
            *(const uint4*)(g_A + (size_t)(rowbase + row) * DIMS + kv * 8);
    }

    unsigned as_u32 = (unsigned)__cvta_generic_to_shared(As);
    unsigned cs_u32 = (unsigned)__cvta_generic_to_shared(Cs);
    unsigned aAddr[2], bAddr[2];
    {
        int arow = (lane & 7) + ((lane >> 3) & 1) * 8;
        int acol = (lane >> 4) * 8;
        #pragma unroll
        for (int mb = 0; mb < 2; mb++)
            aAddr[mb] = as_u32 + ((wr * 32 + mb * 16 + arow) * 264 + acol) * 2;
        int brow = ((lane >> 4) & 1) * 8 + (lane & 7);
        int bcol = ((lane >> 3) & 1) * 8;
        #pragma unroll
        for (int pr = 0; pr < 2; pr++)
            bAddr[pr] = cs_u32 + ((wc * 32 + pr * 16 + brow) * 264 + bcol) * 2;
    }

    float Sacc[2][2] = {{0.f, 0.f}, {0.f, 0.f}};
    float Pacc[2][2] = {{0.f, 0.f}, {0.f, 0.f}};
    int rlab[2][2], grow[2][2];
    #pragma unroll
    for (int mb = 0; mb < 2; mb++)
        #pragma unroll
        for (int p = 0; p < 2; p++) {
            int r = rowbase + wr * 32 + mb * 16 + g + 8 * p;
            grow[mb][p] = r;
            rlab[mb][p] = (r < NA) ? (r / KPC) : -2;
        }

    // prefetch first subtile into registers
    uint4 pre[8];
    int   prelab = 0;
    {
        const int colbase = chunk * 64;
        #pragma unroll
        for (int it = 0; it < 8; it++)
            pre[it] = *(const uint4*)(g_C + (size_t)(colbase + ld_row + it * 8) * DIMS + ld_kv * 8);
        if (tid < 64) prelab = g_clab[colbase + tid];
    }

    for (int s = chunk; s < NSUB; s += COL_CHUNKS) {
        const int colbase = s * 64;
        const bool edge = (colbase + 64 > NCOLS) ||
                          ((colbase < rowbase + 128) && (colbase + 64 > rowbase));
        __syncthreads();
        #pragma unroll
        for (int it = 0; it < 8; it++)
            *(uint4*)(Cs + (ld_row + it * 8) * 264 + ld_kv * 8) = pre[it];
        if (tid < 64) clab_sm[tid] = prelab;
        __syncthreads();

        const int ns = s + COL_CHUNKS;
        if (ns < NSUB) {
            const int ncb = ns * 64;
            #pragma unroll
            for (int it = 0; it < 8; it++)
                pre[it] = *(const uint4*)(g_C + (size_t)(ncb + ld_row + it * 8) * DIMS + ld_kv * 8);
            if (tid < 64) prelab = g_clab[ncb + tid];
        }

        float acc[2][4][4];
        #pragma unroll
        for (int mb = 0; mb < 2; mb++)
            #pragma unroll
            for (int nb = 0; nb < 4; nb++)
                #pragma unroll
                for (int q = 0; q < 4; q++) acc[mb][nb][q] = 0.f;

        #pragma unroll
        for (int k = 0; k < DIMS; k += 16) {
            unsigned a[2][4], b[4][2];
            #pragma unroll
            for (int mb = 0; mb < 2; mb++)
                ldsm_x4(a[mb][0], a[mb][1], a[mb][2], a[mb][3], aAddr[mb] + k * 2);
            #pragma unroll
            for (int pr = 0; pr < 2; pr++)
                ldsm_x4(b[2 * pr][0], b[2 * pr][1], b[2 * pr + 1][0], b[2 * pr + 1][1],
                        bAddr[pr] + k * 2);
            #pragma unroll
            for (int mb = 0; mb < 2; mb++)
                #pragma unroll
                for (int nb = 0; nb < 4; nb++)
                    mma_bf16(acc[mb][nb], a[mb], b[nb]);
        }

        int labreg[8];
        #pragma unroll
        for (int nb = 0; nb < 4; nb++)
            #pragma unroll
            for (int e = 0; e < 2; e++)
                labreg[nb * 2 + e] = clab_sm[wc * 32 + nb * 8 + t2 + e];

        if (!edge) {
            #pragma unroll
            for (int mb = 0; mb < 2; mb++)
                #pragma unroll
                for (int nb = 0; nb < 4; nb++)
                    #pragma unroll
                    for (int p = 0; p < 2; p++)
                        #pragma unroll
                        for (int e = 0; e < 2; e++)
                            ep_core(acc[mb][nb][2 * p + e], labreg[nb * 2 + e],
                                    rlab[mb][p], Sacc[mb][p], Pacc[mb][p]);
        } else {
            #pragma unroll
            for (int mb = 0; mb < 2; mb++)
                #pragma unroll
                for (int nb = 0; nb < 4; nb++) {
                    int colb = wc * 32 + nb * 8 + t2;
                    #pragma unroll
                    for (int p = 0; p < 2; p++)
                        #pragma unroll
                        for (int e = 0; e < 2; e++) {
                            int gcol = colbase + colb + e;
                            if (gcol < NCOLS && gcol != grow[mb][p])
                                ep_core(acc[mb][nb][2 * p + e], labreg[nb * 2 + e],
                                        rlab[mb][p], Sacc[mb][p], Pacc[mb][p]);
                        }
                }
        }
    }

    #pragma unroll
    for (int mb = 0; mb < 2; mb++)
        #pragma unroll
        for (int p = 0; p < 2; p++) {
            float sv = Sacc[mb][p], pv = Pacc[mb][p];
            sv += __shfl_xor_sync(0xffffffffu, sv, 1);
            sv += __shfl_xor_sync(0xffffffffu, sv, 2);
            pv += __shfl_xor_sync(0xffffffffu, pv, 1);
            pv += __shfl_xor_sync(0xffffffffu, pv, 2);
            if ((lane & 3) == 0) {
                int row = wr * 32 + mb * 16 + g + 8 * p;
                redS[row * 2 + wc] = sv;
                redP[row * 2 + wc] = pv;
            }
        }
    __syncthreads();
    if (tid < 128) {
        int r = rowbase + tid;
        g_Sp[r * COL_CHUNKS + chunk] = redS[tid * 2] + redS[tid * 2 + 1];
        g_Pp[r * COL_CHUNKS + chunk] = redP[tid * 2] + redP[tid * 2 + 1];
    }

    // ---- last-block final reduction ----
    __shared__ int sdone;
    __syncthreads();
    __threadfence();
    if (tid == 0) {
        unsigned v = atomicAdd(&g_done, 1u);
        sdone = (v == NBLOCKS - 1);
    }
    __syncthreads();
    if (!sdone) return;

    float local = 0.f;
    for (int n = tid; n < NA; n += 256) {
        float S = 0.f, P = 0.f;
        #pragma unroll
        for (int ch = 0; ch < COL_CHUNKS; ch++) {
            S += g_Sp[n * COL_CHUNKS + ch];
            P += g_Pp[n * COL_CHUNKS + ch];
        }
        float cnt = (float)(KPC - 1 + g_cnt[n / KPC]);
        local += (TEMP_INV * P - cnt * logf(S + 1e-12f)) / cnt;
    }
    redS[tid] = local;
    __syncthreads();
    for (int off = 128; off; off >>= 1) {
        if (tid < off) redS[tid] += redS[tid + off];
        __syncthreads();
    }
    if (tid == 0) {
        out[0] = -LOSS_SCALE * redS[0] / (float)NA;
        g_done = 0;                     // reset for next graph replay
    }
}

// -------------------- launch --------------------
extern "C" void kernel_launch(void* const* d_in, const int* in_sizes, int n_in,
                              void* d_out, int out_size) {
    (void)in_sizes; (void)n_in; (void)out_size;
    const float* pf   = (const float*)d_in[0];
    const void*  lab  = d_in[1];
    const float* mf   = (const float*)d_in[2];
    const void*  mlab = d_in[3];
    float* out = (float*)d_out;

    cudaFuncSetAttribute(k_main, cudaFuncAttributeMaxDynamicSharedMemorySize, SMEM_BYTES);

    k_sample<<<1, 1024>>>((const int*)lab, lab);
    k_prep<<<ANCHOR_BLOCKS + MEM_BLOCKS, 256>>>(pf, mf, mlab);
    k_main<<<dim3(COL_CHUNKS, ROW_TILES), 256, SMEM_BYTES>>>(out);
}

// round 17
// speedup vs baseline: 1.1029x; 1.0822x over previous
#include <cuda_runtime.h>
#include <cuda_bf16.h>
#include <math.h>
#include <stdint.h>

#define NUM_CLASSES 19
#define KPC 100
#define NA 1900
#define NA_PAD 1920
#define NMEM 20000
#define NCOLS 21900
#define NC_PAD 21952
#define DIMS 256
#define HW 16384
#define LBLK 1024
#define NLBLK 128
#define ROW_TILES 15
#define COL_CHUNKS 20
#define NSUB 343
#define NBLOCKS (COL_CHUNKS * ROW_TILES)
#define CNT_STRIDE 64
#define TEMP_INV 10.0f
#define L2E10 14.426950408889634f
#define LOSS_SCALE 1.4285714285714286f

// -------------------- device scratch --------------------
__device__ int g_idx[NA];
__device__ int g_cnt[NUM_CLASSES * CNT_STRIDE];   // strided: 1 counter per 256B (L2 slice spread)
__device__ unsigned g_done;
__device__ __align__(16) __nv_bfloat16 g_A[NA_PAD * DIMS];
__device__ __align__(16) __nv_bfloat16 g_C[NC_PAD * DIMS];
__device__ int g_clab[NC_PAD];
__device__ float g_Sp[NA_PAD * COL_CHUNKS];
__device__ float g_Pp[NA_PAD * COL_CHUNKS];

// MUFU-based exp-and-accumulate: S += 2^(acc*10*log2e), P += acc if labels match.
__device__ __forceinline__ void ep_core(float acc_v, int labv, int rl, float& S, float& P) {
    float e;
    asm("ex2.approx.f32 %0, %1;" : "=f"(e) : "f"(acc_v * L2E10));
    S += e;
    if (labv == rl) P += acc_v;
}

__device__ __forceinline__ void mma_bf16(float* d, const unsigned* a, const unsigned* b) {
    asm volatile(
        "mma.sync.aligned.m16n8k16.row.col.f32.bf16.bf16.f32 "
        "{%0,%1,%2,%3}, {%4,%5,%6,%7}, {%8,%9}, {%0,%1,%2,%3};\n"
        : "+f"(d[0]), "+f"(d[1]), "+f"(d[2]), "+f"(d[3])
        : "r"(a[0]), "r"(a[1]), "r"(a[2]), "r"(a[3]), "r"(b[0]), "r"(b[1]));
}

__device__ __forceinline__ void ldsm_x4(unsigned& r0, unsigned& r1, unsigned& r2,
                                        unsigned& r3, unsigned addr) {
    asm volatile("ldmatrix.sync.aligned.m8n8.x4.shared.b16 {%0,%1,%2,%3}, [%4];"
                 : "=r"(r0), "=r"(r1), "=r"(r2), "=r"(r3) : "r"(addr));
}

// -------------------- k_head: block 0 = label scan; blocks 1.. = memory prep ----
// 1024 threads per block.
#define MEMB_ROWS 32
#define MEM_HEAD_BLOCKS ((NC_PAD - NA + MEMB_ROWS - 1) / MEMB_ROWS)   // 627

__global__ void __launch_bounds__(1024) k_head(const int* lab32, const void* labels,
                                               const float* __restrict__ mf,
                                               const void* mlab) {
    __shared__ int sis64;
    int tid  = threadIdx.x;
    int lane = tid & 31;
    int w    = tid >> 5;

    // per-block dtype detect (64 high words via warp 0; P[false int64 on int32] ~ (1/19)^64)
    if (w == 0) {
        int bad = (lab32[2 * lane + 1] != 0) | (lab32[2 * (lane + 32) + 1] != 0);
        unsigned m = __ballot_sync(0xffffffffu, bad != 0);
        if (lane == 0) sis64 = (m == 0) ? 1 : 0;
    }
    __syncthreads();
    const int is64 = sis64;

    if (blockIdx.x == 0) {
        // ---------------- sampling scan ----------------
        __shared__ int slab[LBLK];
        __shared__ int squit;
        int r = 0;
        unsigned below = (1u << lane) - 1u;

        int v;
        if (is64) v = (int)((const long long*)labels)[tid];
        else      v = ((const int*)labels)[tid];

        for (int c = 0; c < NLBLK; c++) {
            int base = c * LBLK;
            if (tid == 0) squit = 1;
            slab[tid] = v;
            __syncthreads();
            if (c + 1 < NLBLK) {      // prefetch next chunk over the scan phase
                int ni = base + LBLK + tid;
                if (is64) v = (int)((const long long*)labels)[ni];
                else      v = ((const int*)labels)[ni];
            }

            if (w < NUM_CLASSES && r < KPC) {
                #pragma unroll 4
                for (int s = 0; s < 32; s++) {
                    int lv = slab[s * 32 + lane];
                    unsigned m = __ballot_sync(0xffffffffu, lv == w);
                    if (lv == w) {
                        int rank = r + __popc(m & below);
                        if (rank < KPC) g_idx[w * KPC + rank] = base + s * 32 + lane;
                    }
                    r += __popc(m);
                    if (r >= KPC) break;
                }
            }
            if (w < NUM_CLASSES && lane == 0 && r < KPC) squit = 0;
            __syncthreads();
            if (squit) break;
        }
    } else {
        // ---------------- memory normalize + labels + strided histogram ----------
        int m = (blockIdx.x - 1) * MEMB_ROWS + w;
        if (m >= NC_PAD - NA) return;
        float v[8];
        if (m < NMEM) {
            const float* src = mf + (size_t)m * DIMS;
            #pragma unroll
            for (int j = 0; j < 8; j++) v[j] = src[lane + 32 * j];
        } else {
            #pragma unroll
            for (int j = 0; j < 8; j++) v[j] = 0.f;
        }
        float ss = 0.f;
        #pragma unroll
        for (int j = 0; j < 8; j++) ss += v[j] * v[j];
        #pragma unroll
        for (int o = 16; o; o >>= 1) ss += __shfl_xor_sync(0xffffffffu, ss, o);
        float sc = (m < NMEM) ? (1.f / fmaxf(sqrtf(ss), 1e-12f)) : 0.f;
        #pragma unroll
        for (int j = 0; j < 8; j++)
            g_C[(size_t)(NA + m) * DIMS + lane + 32 * j] = __float2bfloat16(v[j] * sc);
        if (lane == 0) {
            int lab = -1;
            if (m < NMEM)
                lab = is64 ? (int)((const long long*)mlab)[m] : ((const int*)mlab)[m];
            g_clab[NA + m] = lab;
            if (lab >= 0) atomicAdd(&g_cnt[lab * CNT_STRIDE], 1);
        }
    }
}

// -------------------- anchors: gather + normalize --------------------
__global__ void k_anchor(const float* __restrict__ pf) {
    int wid  = threadIdx.x >> 5;
    int lane = threadIdx.x & 31;
    int n = blockIdx.x * 8 + wid;
    float v[8];
    if (n < NA) {
        int idx = g_idx[n];
        int b   = idx >> 14;
        int rem = idx & (HW - 1);
        const float* src = pf + (size_t)b * (DIMS * HW) + rem;
        #pragma unroll
        for (int j = 0; j < 8; j++)
            v[j] = src[(size_t)(lane + 32 * j) * HW];
    } else {
        #pragma unroll
        for (int j = 0; j < 8; j++) v[j] = 0.f;
    }
    float ss = 0.f;
    #pragma unroll
    for (int j = 0; j < 8; j++) ss += v[j] * v[j];
    #pragma unroll
    for (int o = 16; o; o >>= 1) ss += __shfl_xor_sync(0xffffffffu, ss, o);
    float sc = (n < NA) ? (1.f / fmaxf(sqrtf(ss), 1e-12f)) : 0.f;
    #pragma unroll
    for (int j = 0; j < 8; j++) {
        __nv_bfloat16 o16 = __float2bfloat16(v[j] * sc);
        int d = lane + 32 * j;
        g_A[n * DIMS + d] = o16;
        g_C[n * DIMS + d] = o16;
    }
    if (lane == 0 && n < NA) g_clab[n] = n / KPC;
}

// -------------------- fused GEMM + softmax reductions + last-block final ----
extern __shared__ char smem_raw[];

#define AS_BYTES (128 * 264 * 2)
#define CS_BYTES (64 * 264 * 2)
#define SMEM_BYTES (AS_BYTES + CS_BYTES + 64 * 4 + 2 * 256 * 4)

__global__ void __launch_bounds__(256) k_main(float* __restrict__ out) {
    __nv_bfloat16* As = (__nv_bfloat16*)smem_raw;                        // [128][264]
    __nv_bfloat16* Cs = (__nv_bfloat16*)(smem_raw + AS_BYTES);           // [64][264]
    int*   clab_sm = (int*)(smem_raw + AS_BYTES + CS_BYTES);             // [64]
    float* redS    = (float*)(smem_raw + AS_BYTES + CS_BYTES + 64 * 4);  // [128][2]
    float* redP    = redS + 256;

    const int tid     = threadIdx.x;
    const int chunk   = blockIdx.x;
    const int rowbase = blockIdx.y * 128;
    const int lane = tid & 31;
    const int w    = tid >> 5;
    const int wr   = w >> 1;
    const int wc   = w & 1;
    const int g    = lane >> 2;
    const int t2   = (lane & 3) * 2;

    const int ld_row = tid >> 5;
    const int ld_kv  = tid & 31;

    // A tile [128][256]
    #pragma unroll
    for (int it = 0; it < 16; it++) {
        int lin = tid + it * 256;
        int row = lin >> 5;
        int kv  = lin & 31;
        *(uint4*)(As + row * 264 + kv * 8) =
            *(const uint4*)(g_A + (size_t)(rowbase + row) * DIMS + kv * 8);
    }

    unsigned as_u32 = (unsigned)__cvta_generic_to_shared(As);
    unsigned cs_u32 = (unsigned)__cvta_generic_to_shared(Cs);
    unsigned aAddr[2], bAddr[2];
    {
        int arow = (lane & 7) + ((lane >> 3) & 1) * 8;
        int acol = (lane >> 4) * 8;
        #pragma unroll
        for (int mb = 0; mb < 2; mb++)
            aAddr[mb] = as_u32 + ((wr * 32 + mb * 16 + arow) * 264 + acol) * 2;
        int brow = ((lane >> 4) & 1) * 8 + (lane & 7);
        int bcol = ((lane >> 3) & 1) * 8;
        #pragma unroll
        for (int pr = 0; pr < 2; pr++)
            bAddr[pr] = cs_u32 + ((wc * 32 + pr * 16 + brow) * 264 + bcol) * 2;
    }

    float Sacc[2][2] = {{0.f, 0.f}, {0.f, 0.f}};
    float Pacc[2][2] = {{0.f, 0.f}, {0.f, 0.f}};
    int rlab[2][2], grow[2][2];
    #pragma unroll
    for (int mb = 0; mb < 2; mb++)
        #pragma unroll
        for (int p = 0; p < 2; p++) {
            int r = rowbase + wr * 32 + mb * 16 + g + 8 * p;
            grow[mb][p] = r;
            rlab[mb][p] = (r < NA) ? (r / KPC) : -2;
        }

    // prefetch first subtile into registers
    uint4 pre[8];
    int   prelab = 0;
    {
        const int colbase = chunk * 64;
        #pragma unroll
        for (int it = 0; it < 8; it++)
            pre[it] = *(const uint4*)(g_C + (size_t)(colbase + ld_row + it * 8) * DIMS + ld_kv * 8);
        if (tid < 64) prelab = g_clab[colbase + tid];
    }

    for (int s = chunk; s < NSUB; s += COL_CHUNKS) {
        const int colbase = s * 64;
        const bool edge = (colbase + 64 > NCOLS) ||
                          ((colbase < rowbase + 128) && (colbase + 64 > rowbase));
        __syncthreads();
        #pragma unroll
        for (int it = 0; it < 8; it++)
            *(uint4*)(Cs + (ld_row + it * 8) * 264 + ld_kv * 8) = pre[it];
        if (tid < 64) clab_sm[tid] = prelab;
        __syncthreads();

        const int ns = s + COL_CHUNKS;
        if (ns < NSUB) {
            const int ncb = ns * 64;
            #pragma unroll
            for (int it = 0; it < 8; it++)
                pre[it] = *(const uint4*)(g_C + (size_t)(ncb + ld_row + it * 8) * DIMS + ld_kv * 8);
            if (tid < 64) prelab = g_clab[ncb + tid];
        }

        float acc[2][4][4];
        #pragma unroll
        for (int mb = 0; mb < 2; mb++)
            #pragma unroll
            for (int nb = 0; nb < 4; nb++)
                #pragma unroll
                for (int q = 0; q < 4; q++) acc[mb][nb][q] = 0.f;

        #pragma unroll
        for (int k = 0; k < DIMS; k += 16) {
            unsigned a[2][4], b[4][2];
            #pragma unroll
            for (int mb = 0; mb < 2; mb++)
                ldsm_x4(a[mb][0], a[mb][1], a[mb][2], a[mb][3], aAddr[mb] + k * 2);
            #pragma unroll
            for (int pr = 0; pr < 2; pr++)
                ldsm_x4(b[2 * pr][0], b[2 * pr][1], b[2 * pr + 1][0], b[2 * pr + 1][1],
                        bAddr[pr] + k * 2);
            #pragma unroll
            for (int mb = 0; mb < 2; mb++)
                #pragma unroll
                for (int nb = 0; nb < 4; nb++)
                    mma_bf16(acc[mb][nb], a[mb], b[nb]);
        }

        int labreg[8];
        #pragma unroll
        for (int nb = 0; nb < 4; nb++)
            #pragma unroll
            for (int e = 0; e < 2; e++)
                labreg[nb * 2 + e] = clab_sm[wc * 32 + nb * 8 + t2 + e];

        if (!edge) {
            #pragma unroll
            for (int mb = 0; mb < 2; mb++)
                #pragma unroll
                for (int nb = 0; nb < 4; nb++)
                    #pragma unroll
                    for (int p = 0; p < 2; p++)
                        #pragma unroll
                        for (int e = 0; e < 2; e++)
                            ep_core(acc[mb][nb][2 * p + e], labreg[nb * 2 + e],
                                    rlab[mb][p], Sacc[mb][p], Pacc[mb][p]);
        } else {
            #pragma unroll
            for (int mb = 0; mb < 2; mb++)
                #pragma unroll
                for (int nb = 0; nb < 4; nb++) {
                    int colb = wc * 32 + nb * 8 + t2;
                    #pragma unroll
                    for (int p = 0; p < 2; p++)
                        #pragma unroll
                        for (int e = 0; e < 2; e++) {
                            int gcol = colbase + colb + e;
                            if (gcol < NCOLS && gcol != grow[mb][p])
                                ep_core(acc[mb][nb][2 * p + e], labreg[nb * 2 + e],
                                        rlab[mb][p], Sacc[mb][p], Pacc[mb][p]);
                        }
                }
        }
    }

    #pragma unroll
    for (int mb = 0; mb < 2; mb++)
        #pragma unroll
        for (int p = 0; p < 2; p++) {
            float sv = Sacc[mb][p], pv = Pacc[mb][p];
            sv += __shfl_xor_sync(0xffffffffu, sv, 1);
            sv += __shfl_xor_sync(0xffffffffu, sv, 2);
            pv += __shfl_xor_sync(0xffffffffu, pv, 1);
            pv += __shfl_xor_sync(0xffffffffu, pv, 2);
            if ((lane & 3) == 0) {
                int row = wr * 32 + mb * 16 + g + 8 * p;
                redS[row * 2 + wc] = sv;
                redP[row * 2 + wc] = pv;
            }
        }
    __syncthreads();
    if (tid < 128) {
        int r = rowbase + tid;
        g_Sp[r * COL_CHUNKS + chunk] = redS[tid * 2] + redS[tid * 2 + 1];
        g_Pp[r * COL_CHUNKS + chunk] = redP[tid * 2] + redP[tid * 2 + 1];
    }

    // ---- last-block final reduction ----
    __shared__ int sdone;
    __syncthreads();
    __threadfence();
    if (tid == 0) {
        unsigned v = atomicAdd(&g_done, 1u);
        sdone = (v == NBLOCKS - 1);
    }
    __syncthreads();
    if (!sdone) return;

    float local = 0.f;
    for (int n = tid; n < NA; n += 256) {
        float S = 0.f, P = 0.f;
        #pragma unroll
        for (int ch = 0; ch < COL_CHUNKS; ch++) {
            S += g_Sp[n * COL_CHUNKS + ch];
            P += g_Pp[n * COL_CHUNKS + ch];
        }
        float cnt = (float)(KPC - 1 + g_cnt[(n / KPC) * CNT_STRIDE]);
        local += (TEMP_INV * P - cnt * logf(S + 1e-12f)) / cnt;
    }
    redS[tid] = local;
    __syncthreads();
    for (int off = 128; off; off >>= 1) {
        if (tid < off) redS[tid] += redS[tid + off];
        __syncthreads();
    }
    // all reads of g_cnt complete (barriers above); reset state for next replay
    if (tid < NUM_CLASSES) g_cnt[tid * CNT_STRIDE] = 0;
    if (tid == 0) {
        out[0] = -LOSS_SCALE * redS[0] / (float)NA;
        g_done = 0;
    }
}

// -------------------- launch --------------------
extern "C" void kernel_launch(void* const* d_in, const int* in_sizes, int n_in,
                              void* d_out, int out_size) {
    (void)in_sizes; (void)n_in; (void)out_size;
    const float* pf   = (const float*)d_in[0];
    const void*  lab  = d_in[1];
    const float* mf   = (const float*)d_in[2];
    const void*  mlab = d_in[3];
    float* out = (float*)d_out;

    cudaFuncSetAttribute(k_main, cudaFuncAttributeMaxDynamicSharedMemorySize, SMEM_BYTES);

    k_head<<<1 + MEM_HEAD_BLOCKS, 1024>>>((const int*)lab, lab, mf, mlab);
    k_anchor<<<NA_PAD / 8, 256>>>(pf);
    k_main<<<dim3(COL_CHUNKS, ROW_TILES), 256, SMEM_BYTES>>>(out);
}